// round 16
// baseline (speedup 1.0000x reference)
#include <cuda_runtime.h>
#include <cuda_fp16.h>
#include <math_constants.h>
#include <cstdint>

// ---------------------------------------------------------------------------
// CausalAttention B=8, N=2048, d=1024, fp32 I/O — fp16 mma.sync path.
// R15: R13 config (best passing, 566.8us) + compact triangular scores grid
// (1088 dense CTAs instead of 2048 half-empty). Streams kept at 1+1 (the
// 4-stream R14 variant violated the graph-teardown memory rule).
// ---------------------------------------------------------------------------

#define BB   8
#define SEQ  2048
#define DIM  1024
#define MTOT (BB * SEQ)

__device__ __half g_Xr[(size_t)MTOT * DIM];
__device__ __half g_Wt[3][(size_t)DIM * DIM];
__device__ __half g_Q [(size_t)MTOT * DIM];
__device__ __half g_K [(size_t)MTOT * DIM];
__device__ __half g_V [(size_t)MTOT * DIM];
__device__ __half g_S [(size_t)BB * SEQ * SEQ];

__device__ __forceinline__ uint32_t smem_u32(const void* p) {
    uint32_t a;
    asm("{ .reg .u64 t; cvta.to.shared.u64 t, %1; cvt.u32.u64 %0, t; }"
        : "=r"(a) : "l"(p));
    return a;
}

#define CP_ASYNC16(dst, src) \
    asm volatile("cp.async.cg.shared.global [%0], [%1], 16;" :: "r"(dst), "l"(src) : "memory")
#define CP_COMMIT()  asm volatile("cp.async.commit_group;" ::: "memory")
#define CP_WAIT(n)   asm volatile("cp.async.wait_group %0;" :: "n"(n) : "memory")

#define LDSM4(r0, r1, r2, r3, addr) \
    asm volatile("ldmatrix.sync.aligned.m8n8.x4.shared.b16 {%0,%1,%2,%3}, [%4];" \
                 : "=r"(r0), "=r"(r1), "=r"(r2), "=r"(r3) : "r"(addr))
#define LDSM4T(r0, r1, r2, r3, addr) \
    asm volatile("ldmatrix.sync.aligned.m8n8.x4.trans.shared.b16 {%0,%1,%2,%3}, [%4];" \
                 : "=r"(r0), "=r"(r1), "=r"(r2), "=r"(r3) : "r"(addr))

__device__ __forceinline__ void mma_f16(float& c0, float& c1, float& c2, float& c3,
                                        uint32_t a0, uint32_t a1, uint32_t a2, uint32_t a3,
                                        uint32_t b0, uint32_t b1) {
    asm volatile(
        "mma.sync.aligned.m16n8k16.row.col.f32.f16.f16.f32 "
        "{%0,%1,%2,%3}, {%4,%5,%6,%7}, {%8,%9}, {%0,%1,%2,%3};"
        : "+f"(c0), "+f"(c1), "+f"(c2), "+f"(c3)
        : "r"(a0), "r"(a1), "r"(a2), "r"(a3), "r"(b0), "r"(b1));
}

// ---------------------------------------------------------------------------
// NT core: A,B both K-major. 128 threads = 4 warps (2x2), warp tile 64x64.
// BK=64, KST=72, 2-stage cp.async double buffer, ldmatrix fragments.
// ---------------------------------------------------------------------------
#define BK 64
#define KST 72
#define TILE_H (128 * KST)
#define SMEM_DYN (4 * TILE_H * 2)   // 73728 B -> 3 CTAs/SM

__device__ __forceinline__ void load_tile(uint32_t smBase,
                                          const __half* __restrict__ G,
                                          int ld, int k0, int t) {
#pragma unroll
    for (int i = 0; i < 8; i++) {
        int idx = t + i * 128;
        int row = idx >> 3, seg = idx & 7;
        uint32_t d = smBase + (uint32_t)(row * KST + seg * 8) * 2u;
        CP_ASYNC16(d, G + (size_t)row * ld + k0 + seg * 8);
    }
}

__device__ __forceinline__ void gemm_core(const __half* __restrict__ A,
                                          const __half* __restrict__ B,
                                          void* __restrict__ Cout, int outHalf,
                                          int lda, int ldb, int ldc,
                                          int nChunks, float scale) {
    extern __shared__ __half dsm[];
    const uint32_t smA = smem_u32(dsm);
    const uint32_t smB = smA + 2u * TILE_H * 2u;

    const int t = threadIdx.x;
    const int wid = t >> 5, lane = t & 31;
    const int gid = lane >> 2, t4 = lane & 3;
    const int lr = lane & 7, lm = lane >> 3;
    const int baseM = (wid >> 1) * 64;
    const int baseN = (wid & 1) * 64;

    uint32_t aOff[4], bOff[4];
#pragma unroll
    for (int mt = 0; mt < 4; mt++)
        aOff[mt] = (uint32_t)((baseM + mt * 16 + (lm & 1) * 8 + lr) * KST + (lm >> 1) * 8) * 2u;
#pragma unroll
    for (int p = 0; p < 4; p++)
        bOff[p] = (uint32_t)((baseN + p * 16 + (lm >> 1) * 8 + lr) * KST + (lm & 1) * 8) * 2u;

    float acc[4][8][4] = {};

    load_tile(smA, A, lda, 0, t);
    load_tile(smB, B, ldb, 0, t);
    CP_COMMIT();

    for (int c = 0; c < nChunks; c++) {
        const int s = c & 1;
        if (c + 1 < nChunks) {
            const uint32_t so = (uint32_t)((s ^ 1) * TILE_H) * 2u;
            load_tile(smA + so, A, lda, (c + 1) * BK, t);
            load_tile(smB + so, B, ldb, (c + 1) * BK, t);
            CP_COMMIT();
            CP_WAIT(1);
        } else {
            CP_WAIT(0);
        }
        __syncthreads();

        const uint32_t stA = smA + (uint32_t)s * TILE_H * 2u;
        const uint32_t stB = smB + (uint32_t)s * TILE_H * 2u;

#pragma unroll
        for (int ks = 0; ks < BK / 16; ks++) {
            const uint32_t ko = (uint32_t)ks * 32u;
            uint32_t af[4][4], bf[8][2];
#pragma unroll
            for (int mt = 0; mt < 4; mt++)
                LDSM4(af[mt][0], af[mt][1], af[mt][2], af[mt][3], stA + aOff[mt] + ko);
#pragma unroll
            for (int p = 0; p < 4; p++)
                LDSM4(bf[2 * p][0], bf[2 * p][1], bf[2 * p + 1][0], bf[2 * p + 1][1],
                      stB + bOff[p] + ko);
#pragma unroll
            for (int mt = 0; mt < 4; mt++)
#pragma unroll
                for (int nt = 0; nt < 8; nt++)
                    mma_f16(acc[mt][nt][0], acc[mt][nt][1], acc[mt][nt][2], acc[mt][nt][3],
                            af[mt][0], af[mt][1], af[mt][2], af[mt][3],
                            bf[nt][0], bf[nt][1]);
        }
        __syncthreads();
    }

#pragma unroll
    for (int mt = 0; mt < 4; mt++) {
        const int r0 = baseM + mt * 16 + gid;
#pragma unroll
        for (int nt = 0; nt < 8; nt++) {
            const int col = baseN + nt * 8 + t4 * 2;
            if (outHalf) {
                __half* Ch = (__half*)Cout;
                *(__half2*)(Ch + (size_t)r0 * ldc + col) =
                    __float22half2_rn(make_float2(acc[mt][nt][0] * scale, acc[mt][nt][1] * scale));
                *(__half2*)(Ch + (size_t)(r0 + 8) * ldc + col) =
                    __float22half2_rn(make_float2(acc[mt][nt][2] * scale, acc[mt][nt][3] * scale));
            } else {
                float* Cf = (float*)Cout;
                *(float2*)(Cf + (size_t)r0 * ldc + col) =
                    make_float2(acc[mt][nt][0] * scale, acc[mt][nt][1] * scale);
                *(float2*)(Cf + (size_t)(r0 + 8) * ldc + col) =
                    make_float2(acc[mt][nt][2] * scale, acc[mt][nt][3] * scale);
            }
        }
    }
}

// ---------------------------------------------------------------------------
// NN core for PV: A = P (k-major), B = V ([k][n]) via ldmatrix.trans.
// ---------------------------------------------------------------------------
#define KSTB 136
#define BTILE_H (64 * KSTB)
#define SMEM_PV (2 * TILE_H * 2 + 2 * BTILE_H * 2)   // 71680 B

__device__ __forceinline__ void load_tile_v(uint32_t smBase,
                                            const __half* __restrict__ G,
                                            int ld, int k0, int nBase, int t) {
#pragma unroll
    for (int i = 0; i < 8; i++) {
        int idx = t + i * 128;
        int row = idx >> 4, seg = idx & 15;
        uint32_t d = smBase + (uint32_t)(row * KSTB + seg * 8) * 2u;
        CP_ASYNC16(d, G + (size_t)(k0 + row) * ld + nBase + seg * 8);
    }
}

__device__ __forceinline__ void gemm_core_nn(const __half* __restrict__ A,
                                             const __half* __restrict__ B,
                                             float* __restrict__ Cout,
                                             int lda, int ldb, int ldc, int nBase0,
                                             int nChunks, float scale) {
    extern __shared__ __half dsm[];
    const uint32_t smA = smem_u32(dsm);
    const uint32_t smB = smA + 2u * TILE_H * 2u;

    const int t = threadIdx.x;
    const int wid = t >> 5, lane = t & 31;
    const int gid = lane >> 2, t4 = lane & 3;
    const int lr = lane & 7, lm = lane >> 3;
    const int baseM = (wid >> 1) * 64;
    const int baseN = (wid & 1) * 64;

    uint32_t aOff[4], bOff[4];
#pragma unroll
    for (int mt = 0; mt < 4; mt++)
        aOff[mt] = (uint32_t)((baseM + mt * 16 + (lm & 1) * 8 + lr) * KST + (lm >> 1) * 8) * 2u;
#pragma unroll
    for (int p = 0; p < 4; p++)
        bOff[p] = (uint32_t)(((lm & 1) * 8 + lr) * KSTB + baseN + p * 16 + (lm >> 1) * 8) * 2u;

    float acc[4][8][4] = {};

    load_tile(smA, A, lda, 0, t);
    load_tile_v(smB, B, ldb, 0, nBase0, t);
    CP_COMMIT();

    for (int c = 0; c < nChunks; c++) {
        const int s = c & 1;
        if (c + 1 < nChunks) {
            load_tile(smA + (uint32_t)((s ^ 1) * TILE_H) * 2u, A, lda, (c + 1) * BK, t);
            load_tile_v(smB + (uint32_t)((s ^ 1) * BTILE_H) * 2u, B, ldb, (c + 1) * BK, nBase0, t);
            CP_COMMIT();
            CP_WAIT(1);
        } else {
            CP_WAIT(0);
        }
        __syncthreads();

        const uint32_t stA = smA + (uint32_t)s * TILE_H * 2u;
        const uint32_t stB = smB + (uint32_t)s * BTILE_H * 2u;

#pragma unroll
        for (int ks = 0; ks < BK / 16; ks++) {
            const uint32_t koA = (uint32_t)ks * 32u;
            const uint32_t koB = (uint32_t)ks * 16u * KSTB * 2u;
            uint32_t af[4][4], bf[8][2];
#pragma unroll
            for (int mt = 0; mt < 4; mt++)
                LDSM4(af[mt][0], af[mt][1], af[mt][2], af[mt][3], stA + aOff[mt] + koA);
#pragma unroll
            for (int p = 0; p < 4; p++)
                LDSM4T(bf[2 * p][0], bf[2 * p][1], bf[2 * p + 1][0], bf[2 * p + 1][1],
                       stB + bOff[p] + koB);
#pragma unroll
            for (int mt = 0; mt < 4; mt++)
#pragma unroll
                for (int nt = 0; nt < 8; nt++)
                    mma_f16(acc[mt][nt][0], acc[mt][nt][1], acc[mt][nt][2], acc[mt][nt][3],
                            af[mt][0], af[mt][1], af[mt][2], af[mt][3],
                            bf[nt][0], bf[nt][1]);
        }
        __syncthreads();
    }

#pragma unroll
    for (int mt = 0; mt < 4; mt++) {
        const int r0 = baseM + mt * 16 + gid;
#pragma unroll
        for (int nt = 0; nt < 8; nt++) {
            const int col = baseN + nt * 8 + t4 * 2;
            *(float2*)(Cout + (size_t)r0 * ldc + col) =
                make_float2(acc[mt][nt][0] * scale, acc[mt][nt][1] * scale);
            *(float2*)(Cout + (size_t)(r0 + 8) * ldc + col) =
                make_float2(acc[mt][nt][2] * scale, acc[mt][nt][3] * scale);
        }
    }
}

// ---------------------------------------------------------------------------
// Prep / transpose kernels
// ---------------------------------------------------------------------------
__global__ void __launch_bounds__(256) prep_x(const float* __restrict__ x) {
    size_t i = (size_t)blockIdx.x * 256 + threadIdx.x;
    float4 v = ((const float4*)x)[i];
    ((__half2*)g_Xr)[i * 2]     = __float22half2_rn(make_float2(v.x, v.y));
    ((__half2*)g_Xr)[i * 2 + 1] = __float22half2_rn(make_float2(v.z, v.w));
}

__global__ void __launch_bounds__(256) transpose_w(const float* __restrict__ Wq,
                                                   const float* __restrict__ Wk,
                                                   const float* __restrict__ Wv) {
    __shared__ float tile[32][33];
    const int z = blockIdx.z;
    const float* W = (z == 0) ? Wq : (z == 1) ? Wk : Wv;
    __half* Wt = g_Wt[z];
    const int nBase = blockIdx.x * 32, kBase = blockIdx.y * 32;
    const int tx = threadIdx.x & 31, ty = threadIdx.x >> 5;
#pragma unroll
    for (int r = 0; r < 32; r += 8)
        tile[ty + r][tx] = W[(size_t)(kBase + ty + r) * DIM + nBase + tx];
    __syncthreads();
#pragma unroll
    for (int r = 0; r < 32; r += 8)
        Wt[(size_t)(nBase + ty + r) * DIM + kBase + tx] = __float2half_rn(tile[tx][ty + r]);
}

// ---------------------------------------------------------------------------
// GEMM wrappers: 128 threads, min 3 CTAs/SM.
// ---------------------------------------------------------------------------
__global__ void __launch_bounds__(128, 3) qkv_gemm(int zBase) {
    const int nb = blockIdx.x, mb = blockIdx.y, z = blockIdx.z + zBase;
    const __half* A = g_Xr + (size_t)mb * 128 * DIM;
    const __half* B = g_Wt[z] + (size_t)nb * 128 * DIM;
    __half* outp = (z == 0) ? g_Q : (z == 1) ? g_K : g_V;
    __half* C = outp + (size_t)mb * 128 * DIM + nb * 128;
    gemm_core(A, B, C, 1, DIM, DIM, DIM, DIM / BK, 1.0f);
}

// Compact lower-triangle grid: blockIdx.x in [0,136) -> (ib,jb), jb<=ib.
__global__ void __launch_bounds__(128, 3) scores_gemm() {
    const int l = blockIdx.x;
    const int b = blockIdx.z;
    int ib = (int)((sqrtf(8.0f * (float)l + 1.0f) - 1.0f) * 0.5f);
    while ((ib + 1) * (ib + 2) / 2 <= l) ib++;
    while (ib * (ib + 1) / 2 > l) ib--;
    const int jb = l - ib * (ib + 1) / 2;

    const __half* A = g_Q + ((size_t)b * SEQ + ib * 128) * DIM;
    const __half* B = g_K + ((size_t)b * SEQ + jb * 128) * DIM;
    __half* C = g_S + (size_t)b * SEQ * SEQ + (size_t)ib * 128 * SEQ + jb * 128;
    gemm_core(A, B, C, 1, DIM, DIM, SEQ, DIM / BK, 0.03125f);
}

__global__ void __launch_bounds__(128, 3) pv_gemm(float* __restrict__ Out) {
    const int db = blockIdx.x, ib = blockIdx.y, b = blockIdx.z;
    const __half* A = g_S + (size_t)b * SEQ * SEQ + (size_t)ib * 128 * SEQ;
    const __half* B = g_V + (size_t)b * SEQ * DIM;
    float* C = Out + ((size_t)b * SEQ + ib * 128) * DIM + db * 128;
    gemm_core_nn(A, B, C, SEQ, DIM, DIM, db * 128, (ib + 1) * 128 / BK, 1.0f);
}

// ---------------------------------------------------------------------------
// Causal softmax on half S; zero-pads row to diagonal 128-block boundary.
// ---------------------------------------------------------------------------
__global__ void __launch_bounds__(256) softmax_kernel() {
    const int row = blockIdx.x;
    const int b = row >> 11;
    const int i = row & (SEQ - 1);
    __half* Srow = g_S + (size_t)b * SEQ * SEQ + (size_t)i * SEQ;
    const int L = i + 1;
    const int Lpad = ((i >> 7) + 1) << 7;
    const int t = threadIdx.x;

    float vals[8];
    float mx = -CUDART_INF_F;
#pragma unroll
    for (int r = 0; r < 8; r++) {
        const int j = t + r * 256;
        vals[r] = (j < L) ? __half2float(Srow[j]) : -CUDART_INF_F;
        mx = fmaxf(mx, vals[r]);
    }
    __shared__ float red[256];
    red[t] = mx;
    __syncthreads();
    for (int s = 128; s > 0; s >>= 1) {
        if (t < s) red[t] = fmaxf(red[t], red[t + s]);
        __syncthreads();
    }
    mx = red[0];
    __syncthreads();

    float sum = 0.f;
#pragma unroll
    for (int r = 0; r < 8; r++) {
        const int j = t + r * 256;
        vals[r] = (j < L) ? __expf(vals[r] - mx) : 0.f;
        sum += vals[r];
    }
    red[t] = sum;
    __syncthreads();
    for (int s = 128; s > 0; s >>= 1) {
        if (t < s) red[t] += red[t + s];
        __syncthreads();
    }
    const float inv = 1.f / red[0];
#pragma unroll
    for (int r = 0; r < 8; r++) {
        const int j = t + r * 256;
        if (j < Lpad) Srow[j] = __float2half_rn(vals[r] * inv);
    }
}

// ---------------------------------------------------------------------------
extern "C" void kernel_launch(void* const* d_in, const int* in_sizes, int n_in,
                              void* d_out, int out_size) {
    const float* x  = (const float*)d_in[0];
    const float* Wq = (const float*)d_in[1];
    const float* Wk = (const float*)d_in[2];
    const float* Wv = (const float*)d_in[3];
    float* out = (float*)d_out;

    static int inited = 0;
    static cudaStream_t sV;
    static cudaEvent_t evFork, evJoin;
    if (!inited) {
        cudaFuncSetAttribute(qkv_gemm,    cudaFuncAttributeMaxDynamicSharedMemorySize, SMEM_DYN);
        cudaFuncSetAttribute(scores_gemm, cudaFuncAttributeMaxDynamicSharedMemorySize, SMEM_DYN);
        cudaFuncSetAttribute(pv_gemm,     cudaFuncAttributeMaxDynamicSharedMemorySize, SMEM_PV);
        cudaStreamCreateWithFlags(&sV, cudaStreamNonBlocking);
        cudaEventCreateWithFlags(&evFork, cudaEventDisableTiming);
        cudaEventCreateWithFlags(&evJoin, cudaEventDisableTiming);
        inited = 1;
    }

    prep_x<<<(MTOT * DIM / 4) / 256, 256>>>(x);
    transpose_w<<<dim3(32, 32, 3), 256>>>(Wq, Wk, Wv);
    cudaEventRecord(evFork, 0);

    // side stream: V projection, overlapped with scores + softmax
    cudaStreamWaitEvent(sV, evFork, 0);
    qkv_gemm<<<dim3(DIM / 128, MTOT / 128, 1), 128, SMEM_DYN, sV>>>(2);
    cudaEventRecord(evJoin, sV);

    // main stream: Q,K projection -> scores (compact triangular) -> softmax
    qkv_gemm<<<dim3(DIM / 128, MTOT / 128, 2), 128, SMEM_DYN>>>(0);
    scores_gemm<<<dim3(136, 1, BB), 128, SMEM_DYN>>>();
    softmax_kernel<<<MTOT, 256>>>();

    cudaStreamWaitEvent(0, evJoin, 0);
    pv_gemm<<<dim3(DIM / 128, SEQ / 128, BB), 128, SMEM_PV>>>(out);
}

// round 17
// speedup vs baseline: 1.0153x; 1.0153x over previous
#include <cuda_runtime.h>
#include <cuda_fp16.h>
#include <math_constants.h>
#include <cstdint>

// ---------------------------------------------------------------------------
// CausalAttention B=8, N=2048, d=1024, fp32 I/O — fp16 mma.sync path.
// R17: exact R13 config (best passing 566.8us) + longest-first CTA ordering
// in scores/pv (heavy full-K tiles issue in wave 1, short tiles backfill the
// tail) + 32B/thread prep_x.
// ---------------------------------------------------------------------------

#define BB   8
#define SEQ  2048
#define DIM  1024
#define MTOT (BB * SEQ)

__device__ __half g_Xr[(size_t)MTOT * DIM];
__device__ __half g_Wt[3][(size_t)DIM * DIM];
__device__ __half g_Q [(size_t)MTOT * DIM];
__device__ __half g_K [(size_t)MTOT * DIM];
__device__ __half g_V [(size_t)MTOT * DIM];
__device__ __half g_S [(size_t)BB * SEQ * SEQ];

__device__ __forceinline__ uint32_t smem_u32(const void* p) {
    uint32_t a;
    asm("{ .reg .u64 t; cvta.to.shared.u64 t, %1; cvt.u32.u64 %0, t; }"
        : "=r"(a) : "l"(p));
    return a;
}

#define CP_ASYNC16(dst, src) \
    asm volatile("cp.async.cg.shared.global [%0], [%1], 16;" :: "r"(dst), "l"(src) : "memory")
#define CP_COMMIT()  asm volatile("cp.async.commit_group;" ::: "memory")
#define CP_WAIT(n)   asm volatile("cp.async.wait_group %0;" :: "n"(n) : "memory")

#define LDSM4(r0, r1, r2, r3, addr) \
    asm volatile("ldmatrix.sync.aligned.m8n8.x4.shared.b16 {%0,%1,%2,%3}, [%4];" \
                 : "=r"(r0), "=r"(r1), "=r"(r2), "=r"(r3) : "r"(addr))
#define LDSM4T(r0, r1, r2, r3, addr) \
    asm volatile("ldmatrix.sync.aligned.m8n8.x4.trans.shared.b16 {%0,%1,%2,%3}, [%4];" \
                 : "=r"(r0), "=r"(r1), "=r"(r2), "=r"(r3) : "r"(addr))

__device__ __forceinline__ void mma_f16(float& c0, float& c1, float& c2, float& c3,
                                        uint32_t a0, uint32_t a1, uint32_t a2, uint32_t a3,
                                        uint32_t b0, uint32_t b1) {
    asm volatile(
        "mma.sync.aligned.m16n8k16.row.col.f32.f16.f16.f32 "
        "{%0,%1,%2,%3}, {%4,%5,%6,%7}, {%8,%9}, {%0,%1,%2,%3};"
        : "+f"(c0), "+f"(c1), "+f"(c2), "+f"(c3)
        : "r"(a0), "r"(a1), "r"(a2), "r"(a3), "r"(b0), "r"(b1));
}

// ---------------------------------------------------------------------------
// NT core: A,B both K-major. 128 threads = 4 warps (2x2), warp tile 64x64.
// BK=64, KST=72, 2-stage cp.async double buffer, ldmatrix fragments.
// ---------------------------------------------------------------------------
#define BK 64
#define KST 72
#define TILE_H (128 * KST)
#define SMEM_DYN (4 * TILE_H * 2)   // 73728 B -> 3 CTAs/SM

__device__ __forceinline__ void load_tile(uint32_t smBase,
                                          const __half* __restrict__ G,
                                          int ld, int k0, int t) {
#pragma unroll
    for (int i = 0; i < 8; i++) {
        int idx = t + i * 128;
        int row = idx >> 3, seg = idx & 7;
        uint32_t d = smBase + (uint32_t)(row * KST + seg * 8) * 2u;
        CP_ASYNC16(d, G + (size_t)row * ld + k0 + seg * 8);
    }
}

__device__ __forceinline__ void gemm_core(const __half* __restrict__ A,
                                          const __half* __restrict__ B,
                                          void* __restrict__ Cout, int outHalf,
                                          int lda, int ldb, int ldc,
                                          int nChunks, float scale) {
    extern __shared__ __half dsm[];
    const uint32_t smA = smem_u32(dsm);
    const uint32_t smB = smA + 2u * TILE_H * 2u;

    const int t = threadIdx.x;
    const int wid = t >> 5, lane = t & 31;
    const int gid = lane >> 2, t4 = lane & 3;
    const int lr = lane & 7, lm = lane >> 3;
    const int baseM = (wid >> 1) * 64;
    const int baseN = (wid & 1) * 64;

    uint32_t aOff[4], bOff[4];
#pragma unroll
    for (int mt = 0; mt < 4; mt++)
        aOff[mt] = (uint32_t)((baseM + mt * 16 + (lm & 1) * 8 + lr) * KST + (lm >> 1) * 8) * 2u;
#pragma unroll
    for (int p = 0; p < 4; p++)
        bOff[p] = (uint32_t)((baseN + p * 16 + (lm >> 1) * 8 + lr) * KST + (lm & 1) * 8) * 2u;

    float acc[4][8][4] = {};

    load_tile(smA, A, lda, 0, t);
    load_tile(smB, B, ldb, 0, t);
    CP_COMMIT();

    for (int c = 0; c < nChunks; c++) {
        const int s = c & 1;
        if (c + 1 < nChunks) {
            const uint32_t so = (uint32_t)((s ^ 1) * TILE_H) * 2u;
            load_tile(smA + so, A, lda, (c + 1) * BK, t);
            load_tile(smB + so, B, ldb, (c + 1) * BK, t);
            CP_COMMIT();
            CP_WAIT(1);
        } else {
            CP_WAIT(0);
        }
        __syncthreads();

        const uint32_t stA = smA + (uint32_t)s * TILE_H * 2u;
        const uint32_t stB = smB + (uint32_t)s * TILE_H * 2u;

#pragma unroll
        for (int ks = 0; ks < BK / 16; ks++) {
            const uint32_t ko = (uint32_t)ks * 32u;
            uint32_t af[4][4], bf[8][2];
#pragma unroll
            for (int mt = 0; mt < 4; mt++)
                LDSM4(af[mt][0], af[mt][1], af[mt][2], af[mt][3], stA + aOff[mt] + ko);
#pragma unroll
            for (int p = 0; p < 4; p++)
                LDSM4(bf[2 * p][0], bf[2 * p][1], bf[2 * p + 1][0], bf[2 * p + 1][1],
                      stB + bOff[p] + ko);
#pragma unroll
            for (int mt = 0; mt < 4; mt++)
#pragma unroll
                for (int nt = 0; nt < 8; nt++)
                    mma_f16(acc[mt][nt][0], acc[mt][nt][1], acc[mt][nt][2], acc[mt][nt][3],
                            af[mt][0], af[mt][1], af[mt][2], af[mt][3],
                            bf[nt][0], bf[nt][1]);
        }
        __syncthreads();
    }

#pragma unroll
    for (int mt = 0; mt < 4; mt++) {
        const int r0 = baseM + mt * 16 + gid;
#pragma unroll
        for (int nt = 0; nt < 8; nt++) {
            const int col = baseN + nt * 8 + t4 * 2;
            if (outHalf) {
                __half* Ch = (__half*)Cout;
                *(__half2*)(Ch + (size_t)r0 * ldc + col) =
                    __float22half2_rn(make_float2(acc[mt][nt][0] * scale, acc[mt][nt][1] * scale));
                *(__half2*)(Ch + (size_t)(r0 + 8) * ldc + col) =
                    __float22half2_rn(make_float2(acc[mt][nt][2] * scale, acc[mt][nt][3] * scale));
            } else {
                float* Cf = (float*)Cout;
                *(float2*)(Cf + (size_t)r0 * ldc + col) =
                    make_float2(acc[mt][nt][0] * scale, acc[mt][nt][1] * scale);
                *(float2*)(Cf + (size_t)(r0 + 8) * ldc + col) =
                    make_float2(acc[mt][nt][2] * scale, acc[mt][nt][3] * scale);
            }
        }
    }
}

// ---------------------------------------------------------------------------
// NN core for PV: A = P (k-major), B = V ([k][n]) via ldmatrix.trans.
// ---------------------------------------------------------------------------
#define KSTB 136
#define BTILE_H (64 * KSTB)
#define SMEM_PV (2 * TILE_H * 2 + 2 * BTILE_H * 2)   // 71680 B

__device__ __forceinline__ void load_tile_v(uint32_t smBase,
                                            const __half* __restrict__ G,
                                            int ld, int k0, int nBase, int t) {
#pragma unroll
    for (int i = 0; i < 8; i++) {
        int idx = t + i * 128;
        int row = idx >> 4, seg = idx & 15;
        uint32_t d = smBase + (uint32_t)(row * KSTB + seg * 8) * 2u;
        CP_ASYNC16(d, G + (size_t)(k0 + row) * ld + nBase + seg * 8);
    }
}

__device__ __forceinline__ void gemm_core_nn(const __half* __restrict__ A,
                                             const __half* __restrict__ B,
                                             float* __restrict__ Cout,
                                             int lda, int ldb, int ldc, int nBase0,
                                             int nChunks, float scale) {
    extern __shared__ __half dsm[];
    const uint32_t smA = smem_u32(dsm);
    const uint32_t smB = smA + 2u * TILE_H * 2u;

    const int t = threadIdx.x;
    const int wid = t >> 5, lane = t & 31;
    const int gid = lane >> 2, t4 = lane & 3;
    const int lr = lane & 7, lm = lane >> 3;
    const int baseM = (wid >> 1) * 64;
    const int baseN = (wid & 1) * 64;

    uint32_t aOff[4], bOff[4];
#pragma unroll
    for (int mt = 0; mt < 4; mt++)
        aOff[mt] = (uint32_t)((baseM + mt * 16 + (lm & 1) * 8 + lr) * KST + (lm >> 1) * 8) * 2u;
#pragma unroll
    for (int p = 0; p < 4; p++)
        bOff[p] = (uint32_t)(((lm & 1) * 8 + lr) * KSTB + baseN + p * 16 + (lm >> 1) * 8) * 2u;

    float acc[4][8][4] = {};

    load_tile(smA, A, lda, 0, t);
    load_tile_v(smB, B, ldb, 0, nBase0, t);
    CP_COMMIT();

    for (int c = 0; c < nChunks; c++) {
        const int s = c & 1;
        if (c + 1 < nChunks) {
            load_tile(smA + (uint32_t)((s ^ 1) * TILE_H) * 2u, A, lda, (c + 1) * BK, t);
            load_tile_v(smB + (uint32_t)((s ^ 1) * BTILE_H) * 2u, B, ldb, (c + 1) * BK, nBase0, t);
            CP_COMMIT();
            CP_WAIT(1);
        } else {
            CP_WAIT(0);
        }
        __syncthreads();

        const uint32_t stA = smA + (uint32_t)s * TILE_H * 2u;
        const uint32_t stB = smB + (uint32_t)s * BTILE_H * 2u;

#pragma unroll
        for (int ks = 0; ks < BK / 16; ks++) {
            const uint32_t koA = (uint32_t)ks * 32u;
            const uint32_t koB = (uint32_t)ks * 16u * KSTB * 2u;
            uint32_t af[4][4], bf[8][2];
#pragma unroll
            for (int mt = 0; mt < 4; mt++)
                LDSM4(af[mt][0], af[mt][1], af[mt][2], af[mt][3], stA + aOff[mt] + koA);
#pragma unroll
            for (int p = 0; p < 4; p++)
                LDSM4T(bf[2 * p][0], bf[2 * p][1], bf[2 * p + 1][0], bf[2 * p + 1][1],
                       stB + bOff[p] + koB);
#pragma unroll
            for (int mt = 0; mt < 4; mt++)
#pragma unroll
                for (int nt = 0; nt < 8; nt++)
                    mma_f16(acc[mt][nt][0], acc[mt][nt][1], acc[mt][nt][2], acc[mt][nt][3],
                            af[mt][0], af[mt][1], af[mt][2], af[mt][3],
                            bf[nt][0], bf[nt][1]);
        }
        __syncthreads();
    }

#pragma unroll
    for (int mt = 0; mt < 4; mt++) {
        const int r0 = baseM + mt * 16 + gid;
#pragma unroll
        for (int nt = 0; nt < 8; nt++) {
            const int col = baseN + nt * 8 + t4 * 2;
            *(float2*)(Cout + (size_t)r0 * ldc + col) =
                make_float2(acc[mt][nt][0] * scale, acc[mt][nt][1] * scale);
            *(float2*)(Cout + (size_t)(r0 + 8) * ldc + col) =
                make_float2(acc[mt][nt][2] * scale, acc[mt][nt][3] * scale);
        }
    }
}

// ---------------------------------------------------------------------------
// Prep / transpose kernels
// ---------------------------------------------------------------------------
__global__ void __launch_bounds__(256) prep_x(const float* __restrict__ x) {
    size_t i = (size_t)blockIdx.x * 512 + threadIdx.x * 2;   // 2 float4/thread
#pragma unroll
    for (int r = 0; r < 2; r++) {
        float4 v = ((const float4*)x)[i + r];
        ((__half2*)g_Xr)[(i + r) * 2]     = __float22half2_rn(make_float2(v.x, v.y));
        ((__half2*)g_Xr)[(i + r) * 2 + 1] = __float22half2_rn(make_float2(v.z, v.w));
    }
}

__global__ void __launch_bounds__(256) transpose_w(const float* __restrict__ Wq,
                                                   const float* __restrict__ Wk,
                                                   const float* __restrict__ Wv) {
    __shared__ float tile[32][33];
    const int z = blockIdx.z;
    const float* W = (z == 0) ? Wq : (z == 1) ? Wk : Wv;
    __half* Wt = g_Wt[z];
    const int nBase = blockIdx.x * 32, kBase = blockIdx.y * 32;
    const int tx = threadIdx.x & 31, ty = threadIdx.x >> 5;
#pragma unroll
    for (int r = 0; r < 32; r += 8)
        tile[ty + r][tx] = W[(size_t)(kBase + ty + r) * DIM + nBase + tx];
    __syncthreads();
#pragma unroll
    for (int r = 0; r < 32; r += 8)
        Wt[(size_t)(nBase + ty + r) * DIM + kBase + tx] = __float2half_rn(tile[tx][ty + r]);
}

// ---------------------------------------------------------------------------
// GEMM wrappers: 128 threads, min 3 CTAs/SM.
// ---------------------------------------------------------------------------
__global__ void __launch_bounds__(128, 3) qkv_gemm(int zBase) {
    const int nb = blockIdx.x, mb = blockIdx.y, z = blockIdx.z + zBase;
    const __half* A = g_Xr + (size_t)mb * 128 * DIM;
    const __half* B = g_Wt[z] + (size_t)nb * 128 * DIM;
    __half* outp = (z == 0) ? g_Q : (z == 1) ? g_K : g_V;
    __half* C = outp + (size_t)mb * 128 * DIM + nb * 128;
    gemm_core(A, B, C, 1, DIM, DIM, DIM, DIM / BK, 1.0f);
}

// Pruned grid; heavy rows (large ib) issue first (longest-work-first).
__global__ void __launch_bounds__(128, 3) scores_gemm() {
    const int jb = blockIdx.x;
    const int ib = (SEQ / 128 - 1) - blockIdx.y;   // reversed
    const int b = blockIdx.z;
    if (jb > ib) return;
    const __half* A = g_Q + ((size_t)b * SEQ + ib * 128) * DIM;
    const __half* B = g_K + ((size_t)b * SEQ + jb * 128) * DIM;
    __half* C = g_S + (size_t)b * SEQ * SEQ + (size_t)ib * 128 * SEQ + jb * 128;
    gemm_core(A, B, C, 1, DIM, DIM, SEQ, DIM / BK, 0.03125f);
}

// Longest-work-first: ib reversed so full-K CTAs land in wave 1.
__global__ void __launch_bounds__(128, 3) pv_gemm(float* __restrict__ Out) {
    const int db = blockIdx.x;
    const int ib = (SEQ / 128 - 1) - blockIdx.y;   // reversed
    const int b = blockIdx.z;
    const __half* A = g_S + (size_t)b * SEQ * SEQ + (size_t)ib * 128 * SEQ;
    const __half* B = g_V + (size_t)b * SEQ * DIM;
    float* C = Out + ((size_t)b * SEQ + ib * 128) * DIM + db * 128;
    gemm_core_nn(A, B, C, SEQ, DIM, DIM, db * 128, (ib + 1) * 128 / BK, 1.0f);
}

// ---------------------------------------------------------------------------
// Causal softmax on half S; zero-pads row to diagonal 128-block boundary.
// ---------------------------------------------------------------------------
__global__ void __launch_bounds__(256) softmax_kernel() {
    const int row = blockIdx.x;
    const int b = row >> 11;
    const int i = row & (SEQ - 1);
    __half* Srow = g_S + (size_t)b * SEQ * SEQ + (size_t)i * SEQ;
    const int L = i + 1;
    const int Lpad = ((i >> 7) + 1) << 7;
    const int t = threadIdx.x;

    float vals[8];
    float mx = -CUDART_INF_F;
#pragma unroll
    for (int r = 0; r < 8; r++) {
        const int j = t + r * 256;
        vals[r] = (j < L) ? __half2float(Srow[j]) : -CUDART_INF_F;
        mx = fmaxf(mx, vals[r]);
    }
    __shared__ float red[256];
    red[t] = mx;
    __syncthreads();
    for (int s = 128; s > 0; s >>= 1) {
        if (t < s) red[t] = fmaxf(red[t], red[t + s]);
        __syncthreads();
    }
    mx = red[0];
    __syncthreads();

    float sum = 0.f;
#pragma unroll
    for (int r = 0; r < 8; r++) {
        const int j = t + r * 256;
        vals[r] = (j < L) ? __expf(vals[r] - mx) : 0.f;
        sum += vals[r];
    }
    red[t] = sum;
    __syncthreads();
    for (int s = 128; s > 0; s >>= 1) {
        if (t < s) red[t] += red[t + s];
        __syncthreads();
    }
    const float inv = 1.f / red[0];
#pragma unroll
    for (int r = 0; r < 8; r++) {
        const int j = t + r * 256;
        if (j < Lpad) Srow[j] = __float2half_rn(vals[r] * inv);
    }
}

// ---------------------------------------------------------------------------
extern "C" void kernel_launch(void* const* d_in, const int* in_sizes, int n_in,
                              void* d_out, int out_size) {
    const float* x  = (const float*)d_in[0];
    const float* Wq = (const float*)d_in[1];
    const float* Wk = (const float*)d_in[2];
    const float* Wv = (const float*)d_in[3];
    float* out = (float*)d_out;

    static int inited = 0;
    static cudaStream_t sV;
    static cudaEvent_t evFork, evJoin;
    if (!inited) {
        cudaFuncSetAttribute(qkv_gemm,    cudaFuncAttributeMaxDynamicSharedMemorySize, SMEM_DYN);
        cudaFuncSetAttribute(scores_gemm, cudaFuncAttributeMaxDynamicSharedMemorySize, SMEM_DYN);
        cudaFuncSetAttribute(pv_gemm,     cudaFuncAttributeMaxDynamicSharedMemorySize, SMEM_PV);
        cudaStreamCreateWithFlags(&sV, cudaStreamNonBlocking);
        cudaEventCreateWithFlags(&evFork, cudaEventDisableTiming);
        cudaEventCreateWithFlags(&evJoin, cudaEventDisableTiming);
        inited = 1;
    }

    prep_x<<<(MTOT * DIM / 8) / 256, 256>>>(x);
    transpose_w<<<dim3(32, 32, 3), 256>>>(Wq, Wk, Wv);
    cudaEventRecord(evFork, 0);

    // side stream: V projection, overlapped with scores + softmax
    cudaStreamWaitEvent(sV, evFork, 0);
    qkv_gemm<<<dim3(DIM / 128, MTOT / 128, 1), 128, SMEM_DYN, sV>>>(2);
    cudaEventRecord(evJoin, sV);

    // main stream: Q,K projection -> scores -> softmax
    qkv_gemm<<<dim3(DIM / 128, MTOT / 128, 2), 128, SMEM_DYN>>>(0);
    scores_gemm<<<dim3(SEQ / 128, SEQ / 128, BB), 128, SMEM_DYN>>>();
    softmax_kernel<<<MTOT, 256>>>();

    cudaStreamWaitEvent(0, evJoin, 0);
    pv_gemm<<<dim3(DIM / 128, SEQ / 128, BB), 128, SMEM_PV>>>(out);
}